// round 9
// baseline (speedup 1.0000x reference)
#include <cuda_runtime.h>
#include <cuda_bf16.h>
#include <cstdint>

// Problem constants
#define BATCH   2
#define HEADS   16
#define SEQ     2048
#define HD      64
#define DMODEL  1024
#define MROWS   (BATCH * SEQ)   // 4096

// ===========================================================================
// Global scratch (allocation-free rule: __device__ globals). bf16 hi/lo planes.
// ===========================================================================
__device__ __nv_bfloat16 g_xh[MROWS * DMODEL], g_xl[MROWS * DMODEL];
__device__ __nv_bfloat16 g_Wqh[DMODEL * DMODEL], g_Wql[DMODEL * DMODEL];
__device__ __nv_bfloat16 g_Wkh[DMODEL * DMODEL], g_Wkl[DMODEL * DMODEL];
__device__ __nv_bfloat16 g_Wvh[DMODEL * DMODEL], g_Wvl[DMODEL * DMODEL];
__device__ __nv_bfloat16 g_Woh[DMODEL * DMODEL], g_Wol[DMODEL * DMODEL];
__device__ __nv_bfloat16 g_Qh[MROWS * DMODEL], g_Ql[MROWS * DMODEL];  // [B,H,S,HD]
__device__ __nv_bfloat16 g_Kh[MROWS * DMODEL], g_Kl[MROWS * DMODEL];
__device__ __nv_bfloat16 g_Vh[MROWS * DMODEL], g_Vl[MROWS * DMODEL];
__device__ __nv_bfloat16 g_Oh[MROWS * DMODEL], g_Ol[MROWS * DMODEL];  // [B,S,D]

// ===========================================================================
// PTX helpers
// ===========================================================================
// volatile on purpose: keeps ptxas from hoisting/reordering fragment loads
// and MMAs in ways that extend live ranges past the 128-reg cap (R7 lesson).
__device__ __forceinline__ void mma_bf16(float* c, const uint32_t* a,
                                         uint32_t b0, uint32_t b1) {
    asm volatile(
        "mma.sync.aligned.m16n8k16.row.col.f32.bf16.bf16.f32 "
        "{%0,%1,%2,%3}, {%4,%5,%6,%7}, {%8,%9}, {%0,%1,%2,%3};\n"
        : "+f"(c[0]), "+f"(c[1]), "+f"(c[2]), "+f"(c[3])
        : "r"(a[0]), "r"(a[1]), "r"(a[2]), "r"(a[3]), "r"(b0), "r"(b1));
}

__device__ __forceinline__ void ldsm_x4(uint32_t* r, uint32_t addr) {
    asm volatile(
        "ldmatrix.sync.aligned.m8n8.x4.shared.b16 {%0,%1,%2,%3}, [%4];"
        : "=r"(r[0]), "=r"(r[1]), "=r"(r[2]), "=r"(r[3]) : "r"(addr));
}

__device__ __forceinline__ void ldsm_x4_t(uint32_t* r, uint32_t addr) {
    asm volatile(
        "ldmatrix.sync.aligned.m8n8.x4.trans.shared.b16 {%0,%1,%2,%3}, [%4];"
        : "=r"(r[0]), "=r"(r[1]), "=r"(r[2]), "=r"(r[3]) : "r"(addr));
}

__device__ __forceinline__ uint32_t smem_u32(const void* p) {
    uint32_t a;
    asm("{ .reg .u64 t; cvta.to.shared.u64 t, %1; cvt.u32.u64 %0, t; }"
        : "=r"(a) : "l"(p));
    return a;
}

__device__ __forceinline__ void cp_async16(uint32_t dst, const void* src) {
    asm volatile("cp.async.cg.shared.global [%0], [%1], 16;"
                 :: "r"(dst), "l"(src));
}
__device__ __forceinline__ void cp_commit() {
    asm volatile("cp.async.commit_group;");
}
template <int N> __device__ __forceinline__ void cp_wait() {
    asm volatile("cp.async.wait_group %0;" :: "n"(N));
}

__device__ __forceinline__ void split2(float x, float y,
                                       uint32_t& hi, uint32_t& lo) {
    __nv_bfloat16 hx = __float2bfloat16(x);
    __nv_bfloat16 hy = __float2bfloat16(y);
    __nv_bfloat162 h = __halves2bfloat162(hx, hy);
    __nv_bfloat162 l = __halves2bfloat162(
        __float2bfloat16(x - __bfloat162float(hx)),
        __float2bfloat16(y - __bfloat162float(hy)));
    hi = *(uint32_t*)&h;
    lo = *(uint32_t*)&l;
}

// ===========================================================================
// Fused split: all 5 fp32 tensors -> bf16 hi/lo planes in ONE launch.
// ===========================================================================
#define NX4 (MROWS * DMODEL / 4)      // 1048576
#define NW4 (DMODEL * DMODEL / 4)     // 262144 = 2^18
#define NSPLIT4 (NX4 + 4 * NW4)       // 2097152

__global__ __launch_bounds__(256) void split_all(
    const float* __restrict__ x,  const float* __restrict__ wq,
    const float* __restrict__ wk, const float* __restrict__ wv,
    const float* __restrict__ wo)
{
    int i = blockIdx.x * 256 + threadIdx.x;
    if (i >= NSPLIT4) return;
    const float* src;
    __nv_bfloat16 *hi, *lo;
    int j;
    if (i < NX4) {
        src = x; hi = g_xh; lo = g_xl; j = i;
    } else {
        int r = i - NX4;
        int w = r >> 18;
        j = r & (NW4 - 1);
        switch (w) {
            case 0:  src = wq; hi = g_Wqh; lo = g_Wql; break;
            case 1:  src = wk; hi = g_Wkh; lo = g_Wkl; break;
            case 2:  src = wv; hi = g_Wvh; lo = g_Wvl; break;
            default: src = wo; hi = g_Woh; lo = g_Wol; break;
        }
    }
    float4 v = ((const float4*)src)[j];
    uint32_t h0, l0, h1, l1;
    split2(v.x, v.y, h0, l0);
    split2(v.z, v.w, h1, l1);
    ((uint32_t*)hi)[2 * j + 0] = h0;
    ((uint32_t*)hi)[2 * j + 1] = h1;
    ((uint32_t*)lo)[2 * j + 0] = l0;
    ((uint32_t*)lo)[2 * j + 1] = l1;
}

// ===========================================================================
// bf16x2 GEMM: out = A[M,K] @ W[N,K]^T + bias
// CTA 128x128, BK=32, 256 threads (8 warps 4m x 2n). ldmatrix.x4 fragments.
// B fragments single-step software-pipelined (one 16-reg extra buffer);
// MMA ordering identical to R5/R8; all asm volatile (reg-pressure control).
// final=0: z=0/1/2 -> Wq/Wk/Wv, A=x planes, write Q/K/V planes [B,H,S,HD]
// final=1: A=g_O planes, W=Wo, write fp32 out [M,N]
// ===========================================================================
#define GPLB 10240                 // plane bytes: 128 rows * 40 bf16 * 2
#define GSTAGE (4 * GPLB)          // 40960
#define G_SMEM (2 * GSTAGE)        // 81920

__global__ __launch_bounds__(256, 2) void gemm_bf16x2(
    const float* __restrict__ bq, const float* __restrict__ bk,
    const float* __restrict__ bv, const float* __restrict__ bo,
    float* __restrict__ out, int final_)
{
    extern __shared__ char sm[];
    const uint32_t sbase = smem_u32(sm);

    const int mode = final_ ? 0 : (int)blockIdx.z + 1;
    const __nv_bfloat16 *Agh, *Agl, *Bgh, *Bgl;
    const float* bias;
    if (mode == 0)      { Agh = g_Oh; Agl = g_Ol; Bgh = g_Woh; Bgl = g_Wol; bias = bo; }
    else if (mode == 1) { Agh = g_xh; Agl = g_xl; Bgh = g_Wqh; Bgl = g_Wql; bias = bq; }
    else if (mode == 2) { Agh = g_xh; Agl = g_xl; Bgh = g_Wkh; Bgl = g_Wkl; bias = bk; }
    else                { Agh = g_xh; Agl = g_xl; Bgh = g_Wvh; Bgl = g_Wvl; bias = bv; }

    const int tid  = threadIdx.x;
    const int lane = tid & 31;
    const int wid  = tid >> 5;
    const int wm   = wid & 3;
    const int wn   = wid >> 2;
    const int g    = lane >> 2;
    const int t    = lane & 3;
    const int lr   = lane & 15;
    const int lk   = (lane >> 4) << 3;
    const int row0 = blockIdx.y * 128;
    const int col0 = blockIdx.x * 128;

    float acc[2][8][4];
#pragma unroll
    for (int i = 0; i < 2; i++)
#pragma unroll
        for (int j = 0; j < 8; j++)
#pragma unroll
            for (int q = 0; q < 4; q++) acc[i][j][q] = 0.0f;

    auto ld_stage = [&](int s, int kt) {
        const int kb = kt * 32;
        const uint32_t sb2 = sbase + s * GSTAGE;
#pragma unroll
        for (int i = 0; i < 2; i++) {
            int f = tid + i * 256;
            int r = f >> 2;
            int c = (f & 3) * 8;
            uint32_t o2 = (uint32_t)(r * 80 + c * 2);
            size_t ga = (size_t)(row0 + r) * DMODEL + kb + c;
            size_t gb = (size_t)(col0 + r) * DMODEL + kb + c;
            cp_async16(sb2 + o2,             Agh + ga);
            cp_async16(sb2 + GPLB + o2,      Agl + ga);
            cp_async16(sb2 + 2 * GPLB + o2,  Bgh + gb);
            cp_async16(sb2 + 3 * GPLB + o2,  Bgl + gb);
        }
    };

    ld_stage(0, 0);
    cp_commit();

    // B-fragment smem offset for (kk, np) within a stage
    auto b_off = [&](uint32_t stb, int kk, int np) -> uint32_t {
        return stb + 2 * GPLB +
            (uint32_t)(((wn * 64 + np * 16 + lr) * 40 + kk * 16 + lk) * 2);
    };

    const int NS = DMODEL / 32;   // 32
    for (int kt = 0; kt < NS; kt++) {
        if (kt + 1 < NS) {
            ld_stage((kt + 1) & 1, kt + 1);
            cp_commit();
            cp_wait<1>();
        } else {
            cp_wait<0>();
        }
        __syncthreads();

        const uint32_t stb = sbase + (kt & 1) * GSTAGE;

        uint32_t ah[2][4], al[2][4];      // A frags, current kk
        uint32_t bh[2][4], bl[2][4];      // B frags, double-buffered over np

        // kk=0 A fragments
#pragma unroll
        for (int mt = 0; mt < 2; mt++) {
            uint32_t ao = stb +
                (uint32_t)(((wm * 32 + mt * 16 + lr) * 40 + lk) * 2);
            ldsm_x4(ah[mt], ao);
            ldsm_x4(al[mt], ao + GPLB);
        }
        // B(kk=0, np=0) into buffer 0
        {
            uint32_t bo_ = b_off(stb, 0, 0);
            ldsm_x4(bh[0], bo_);
            ldsm_x4(bl[0], bo_ + GPLB);
        }

#pragma unroll
        for (int kk = 0; kk < 2; kk++) {
#pragma unroll
            for (int np = 0; np < 4; np++) {
                const int cur = np & 1;
                const int nxt = cur ^ 1;
                // prefetch next B fragments (overlaps the 12 MMAs below)
                if (np < 3) {
                    uint32_t bo_ = b_off(stb, kk, np + 1);
                    ldsm_x4(bh[nxt], bo_);
                    ldsm_x4(bl[nxt], bo_ + GPLB);
                } else if (kk == 0) {
                    uint32_t bo_ = b_off(stb, 1, 0);
                    ldsm_x4(bh[nxt], bo_);
                    ldsm_x4(bl[nxt], bo_ + GPLB);
                }
                // MMAs — identical ordering to R5/R8
#pragma unroll
                for (int mt = 0; mt < 2; mt++) {
                    mma_bf16(acc[mt][2 * np],     ah[mt], bh[cur][0], bh[cur][2]);
                    mma_bf16(acc[mt][2 * np],     ah[mt], bl[cur][0], bl[cur][2]);
                    mma_bf16(acc[mt][2 * np],     al[mt], bh[cur][0], bh[cur][2]);
                    mma_bf16(acc[mt][2 * np + 1], ah[mt], bh[cur][1], bh[cur][3]);
                    mma_bf16(acc[mt][2 * np + 1], ah[mt], bl[cur][1], bl[cur][3]);
                    mma_bf16(acc[mt][2 * np + 1], al[mt], bh[cur][1], bh[cur][3]);
                }
            }
            // A fragments for kk=1 (after kk=0's MMAs; one short stall/stage)
            if (kk == 0) {
#pragma unroll
                for (int mt = 0; mt < 2; mt++) {
                    uint32_t ao = stb +
                        (uint32_t)(((wm * 32 + mt * 16 + lr) * 40 + 16 + lk) * 2);
                    ldsm_x4(ah[mt], ao);
                    ldsm_x4(al[mt], ao + GPLB);
                }
            }
        }
        __syncthreads();
    }

    // Epilogue
    __nv_bfloat16* Dh = (mode == 1) ? g_Qh : (mode == 2) ? g_Kh : g_Vh;
    __nv_bfloat16* Dl = (mode == 1) ? g_Ql : (mode == 2) ? g_Kl : g_Vl;
#pragma unroll
    for (int mt = 0; mt < 2; mt++) {
#pragma unroll
        for (int h = 0; h < 2; h++) {
            const int m = row0 + wm * 32 + mt * 16 + g + h * 8;
            const int b_ = m >> 11;
            const int s_ = m & 2047;
#pragma unroll
            for (int nt = 0; nt < 8; nt++) {
                const int n = col0 + wn * 64 + nt * 8 + 2 * t;
                float vx = acc[mt][nt][h * 2 + 0] + bias[n + 0];
                float vy = acc[mt][nt][h * 2 + 1] + bias[n + 1];
                if (mode == 0) {
                    float2 v; v.x = vx; v.y = vy;
                    *(float2*)(out + (size_t)m * DMODEL + n) = v;
                } else {
                    const int hh = n >> 6, d = n & 63;
                    size_t idx = (((size_t)(b_ * HEADS + hh)) * SEQ + s_) * HD + d;
                    uint32_t hi, lo;
                    split2(vx, vy, hi, lo);
                    *(uint32_t*)(Dh + idx) = hi;
                    *(uint32_t*)(Dl + idx) = lo;
                }
            }
        }
    }
}

// ===========================================================================
// Flash attention (R5/R8-proven form, untouched), bf16x2 mma, P & Q in regs.
// Grid (SEQ/128, B*H), 256 threads (8 warps), 2 CTAs/SM.
// ===========================================================================
#define AST(st) ((st) * 36864)
#define ATT_SMEM 73728

__global__ __launch_bounds__(256, 2) void attn_bf16x2()
{
    extern __shared__ char sm[];
    const uint32_t sb = smem_u32(sm);

    const int tid  = threadIdx.x;
    const int lane = tid & 31;
    const int wid  = tid >> 5;
    const int g    = lane >> 2;
    const int t    = lane & 3;
    const int lr   = lane & 15;
    const int lh   = lane >> 4;        // 0/1
    const int qt   = blockIdx.x;       // 0..15
    const int bh   = blockIdx.y;       // 0..31

    // ---- Q fragments in registers (loaded once) ----
    uint32_t qh[4][4], ql[4][4];
    {
        const size_t base = ((size_t)bh * SEQ + qt * 128 + wid * 16) * HD;
        const __nv_bfloat16* Qh = g_Qh + base;
        const __nv_bfloat16* Ql = g_Ql + base;
#pragma unroll
        for (int kk = 0; kk < 4; kk++) {
            const int d0 = kk * 16 + 2 * t;
            qh[kk][0] = *(const uint32_t*)(Qh + g * HD + d0);
            qh[kk][1] = *(const uint32_t*)(Qh + (g + 8) * HD + d0);
            qh[kk][2] = *(const uint32_t*)(Qh + g * HD + d0 + 8);
            qh[kk][3] = *(const uint32_t*)(Qh + (g + 8) * HD + d0 + 8);
            ql[kk][0] = *(const uint32_t*)(Ql + g * HD + d0);
            ql[kk][1] = *(const uint32_t*)(Ql + (g + 8) * HD + d0);
            ql[kk][2] = *(const uint32_t*)(Ql + g * HD + d0 + 8);
            ql[kk][3] = *(const uint32_t*)(Ql + (g + 8) * HD + d0 + 8);
        }
    }

    auto ld_kv = [&](int st, int ck) {
        const size_t go = ((size_t)bh * SEQ + (size_t)ck * 64) * HD;
        const uint32_t base = sb + AST(st);
#pragma unroll
        for (int i = 0; i < 2; i++) {
            int f = tid + i * 256;
            int r = f >> 3, c = f & 7;
            uint32_t o2 = (uint32_t)(r * 144 + c * 16);
            size_t gi = go + r * 64 + c * 8;
            cp_async16(base + o2,          g_Kh + gi);
            cp_async16(base + 9216 + o2,   g_Kl + gi);
            cp_async16(base + 18432 + o2,  g_Vh + gi);
            cp_async16(base + 27648 + o2,  g_Vl + gi);
        }
    };

    ld_kv(0, 0); cp_commit();
    ld_kv(1, 1); cp_commit();

    float o[8][4];
#pragma unroll
    for (int nt = 0; nt < 8; nt++)
#pragma unroll
        for (int q = 0; q < 4; q++) o[nt][q] = 0.0f;
    float mrow[2] = {-1e30f, -1e30f};
    float lrow[2] = {0.0f, 0.0f};
    const float scale = 0.125f;

    for (int ck = 0; ck < SEQ / 64; ck++) {
        if (ck >= SEQ / 64 - 2) cp_wait<0>(); else cp_wait<1>();
        __syncthreads();

        const uint32_t kpl = sb + AST(ck & 1);
        const uint32_t vpl = kpl + 18432;

        // ---- QK^T ----
        float s[8][4];
#pragma unroll
        for (int nt = 0; nt < 8; nt++)
#pragma unroll
            for (int q = 0; q < 4; q++) s[nt][q] = 0.0f;

#pragma unroll
        for (int kk = 0; kk < 4; kk++) {
#pragma unroll
            for (int np = 0; np < 4; np++) {
                uint32_t kbh[4], kbl[4];
                uint32_t ko = kpl +
                    (uint32_t)(((np * 16 + lr) * 72 + kk * 16 + lh * 8) * 2);
                ldsm_x4(kbh, ko);
                ldsm_x4(kbl, ko + 9216);
                mma_bf16(s[2 * np],     qh[kk], kbh[0], kbh[2]);
                mma_bf16(s[2 * np],     qh[kk], kbl[0], kbl[2]);
                mma_bf16(s[2 * np],     ql[kk], kbh[0], kbh[2]);
                mma_bf16(s[2 * np + 1], qh[kk], kbh[1], kbh[3]);
                mma_bf16(s[2 * np + 1], qh[kk], kbl[1], kbl[3]);
                mma_bf16(s[2 * np + 1], ql[kk], kbh[1], kbh[3]);
            }
        }

        // ---- online softmax (rows g, g+8; warp-local over t lanes) ----
#pragma unroll
        for (int nt = 0; nt < 8; nt++)
#pragma unroll
            for (int q = 0; q < 4; q++) s[nt][q] *= scale;

#pragma unroll
        for (int h = 0; h < 2; h++) {
            float mx = -1e30f;
#pragma unroll
            for (int nt = 0; nt < 8; nt++) {
                mx = fmaxf(mx, s[nt][h * 2 + 0]);
                mx = fmaxf(mx, s[nt][h * 2 + 1]);
            }
            mx = fmaxf(mx, __shfl_xor_sync(0xffffffffu, mx, 1));
            mx = fmaxf(mx, __shfl_xor_sync(0xffffffffu, mx, 2));
            const float mnew  = fmaxf(mrow[h], mx);
            const float alpha = __expf(mrow[h] - mnew);
            float rsum = 0.0f;
#pragma unroll
            for (int nt = 0; nt < 8; nt++) {
                float p0 = __expf(s[nt][h * 2 + 0] - mnew);
                float p1 = __expf(s[nt][h * 2 + 1] - mnew);
                s[nt][h * 2 + 0] = p0;
                s[nt][h * 2 + 1] = p1;
                rsum += p0 + p1;
            }
            rsum += __shfl_xor_sync(0xffffffffu, rsum, 1);
            rsum += __shfl_xor_sync(0xffffffffu, rsum, 2);
            lrow[h] = lrow[h] * alpha + rsum;
            mrow[h] = mnew;
#pragma unroll
            for (int nt = 0; nt < 8; nt++) {
                o[nt][h * 2 + 0] *= alpha;
                o[nt][h * 2 + 1] *= alpha;
            }
        }

        // ---- O += P @ V  (P repacked C->A frags in registers) ----
#pragma unroll
        for (int kk = 0; kk < 4; kk++) {
            uint32_t ph[4], pl[4];
            split2(s[2 * kk][0],     s[2 * kk][1],     ph[0], pl[0]);
            split2(s[2 * kk][2],     s[2 * kk][3],     ph[1], pl[1]);
            split2(s[2 * kk + 1][0], s[2 * kk + 1][1], ph[2], pl[2]);
            split2(s[2 * kk + 1][2], s[2 * kk + 1][3], ph[3], pl[3]);
#pragma unroll
            for (int np = 0; np < 4; np++) {
                uint32_t vbh[4], vbl[4];
                uint32_t vo = vpl +
                    (uint32_t)((kk * 16 + lr) * 144 + np * 32 + lh * 16);
                ldsm_x4_t(vbh, vo);
                ldsm_x4_t(vbl, vo + 9216);
                mma_bf16(o[2 * np],     ph, vbh[0], vbh[1]);
                mma_bf16(o[2 * np],     ph, vbl[0], vbl[1]);
                mma_bf16(o[2 * np],     pl, vbh[0], vbh[1]);
                mma_bf16(o[2 * np + 1], ph, vbh[2], vbh[3]);
                mma_bf16(o[2 * np + 1], ph, vbl[2], vbl[3]);
                mma_bf16(o[2 * np + 1], pl, vbh[2], vbh[3]);
            }
        }
        __syncthreads();
        if (ck + 2 < SEQ / 64) { ld_kv(ck & 1, ck + 2); cp_commit(); }
    }

    // ---- epilogue: split & write to g_O planes [B,S,D] ----
    const int b_ = bh >> 4;
    const int h_ = bh & 15;
#pragma unroll
    for (int h = 0; h < 2; h++) {
        const float inv = 1.0f / lrow[h];
        const int srow = qt * 128 + wid * 16 + g + h * 8;
        const size_t ro = ((size_t)(b_ * SEQ + srow)) * DMODEL + h_ * 64;
#pragma unroll
        for (int nt = 0; nt < 8; nt++) {
            float vx = o[nt][h * 2 + 0] * inv;
            float vy = o[nt][h * 2 + 1] * inv;
            uint32_t hi, lo;
            split2(vx, vy, hi, lo);
            *(uint32_t*)(g_Oh + ro + nt * 8 + 2 * t) = hi;
            *(uint32_t*)(g_Ol + ro + nt * 8 + 2 * t) = lo;
        }
    }
}

// ---------------------------------------------------------------------------
extern "C" void kernel_launch(void* const* d_in, const int* in_sizes, int n_in,
                              void* d_out, int out_size)
{
    const float* x  = (const float*)d_in[0];
    const float* Wq = (const float*)d_in[1];
    const float* bq = (const float*)d_in[2];
    const float* Wk = (const float*)d_in[3];
    const float* bk = (const float*)d_in[4];
    const float* Wv = (const float*)d_in[5];
    const float* bv = (const float*)d_in[6];
    const float* Wo = (const float*)d_in[7];
    const float* bo = (const float*)d_in[8];
    float* out = (float*)d_out;

    static int attr_set = 0;
    if (!attr_set) {
        cudaFuncSetAttribute(gemm_bf16x2,
                             cudaFuncAttributeMaxDynamicSharedMemorySize,
                             G_SMEM);
        cudaFuncSetAttribute(attn_bf16x2,
                             cudaFuncAttributeMaxDynamicSharedMemorySize,
                             ATT_SMEM);
        attr_set = 1;
    }

    // Fused splits: fp32 -> bf16 hi/lo planes (one launch)
    split_all<<<(NSPLIT4 + 255) / 256, 256>>>(x, Wq, Wk, Wv, Wo);

    // Fused QKV projections (z selects Wq/Wk/Wv)
    gemm_bf16x2<<<dim3(DMODEL / 128, MROWS / 128, 3), 256, G_SMEM>>>(
        bq, bk, bv, nullptr, nullptr, 0);

    attn_bf16x2<<<dim3(SEQ / 128, BATCH * HEADS), 256, ATT_SMEM>>>();

    // Output projection
    gemm_bf16x2<<<dim3(DMODEL / 128, MROWS / 128, 1), 256, G_SMEM>>>(
        nullptr, nullptr, nullptr, bo, out, 1);
}

// round 10
// speedup vs baseline: 1.5349x; 1.5349x over previous
#include <cuda_runtime.h>
#include <cuda_bf16.h>
#include <cstdint>

// Problem constants
#define BATCH   2
#define HEADS   16
#define SEQ     2048
#define HD      64
#define DMODEL  1024
#define MROWS   (BATCH * SEQ)   // 4096

// ===========================================================================
// Global scratch (allocation-free rule: __device__ globals). bf16 hi/lo planes.
// ===========================================================================
__device__ __nv_bfloat16 g_xh[MROWS * DMODEL], g_xl[MROWS * DMODEL];
__device__ __nv_bfloat16 g_Wqh[DMODEL * DMODEL], g_Wql[DMODEL * DMODEL];
__device__ __nv_bfloat16 g_Wkh[DMODEL * DMODEL], g_Wkl[DMODEL * DMODEL];
__device__ __nv_bfloat16 g_Wvh[DMODEL * DMODEL], g_Wvl[DMODEL * DMODEL];
__device__ __nv_bfloat16 g_Woh[DMODEL * DMODEL], g_Wol[DMODEL * DMODEL];
__device__ __nv_bfloat16 g_Qh[MROWS * DMODEL], g_Ql[MROWS * DMODEL];  // [B,H,S,HD]
__device__ __nv_bfloat16 g_Kh[MROWS * DMODEL], g_Kl[MROWS * DMODEL];
__device__ __nv_bfloat16 g_Vh[MROWS * DMODEL], g_Vl[MROWS * DMODEL];
__device__ __nv_bfloat16 g_Oh[MROWS * DMODEL], g_Ol[MROWS * DMODEL];  // [B,S,D]

// ===========================================================================
// PTX helpers
// ===========================================================================
// volatile on purpose: keeps ptxas from hoisting/reordering fragment loads
// in ways that extend live ranges past the 128-reg cap (R7/R9 lesson).
__device__ __forceinline__ void mma_bf16(float* c, const uint32_t* a,
                                         uint32_t b0, uint32_t b1) {
    asm volatile(
        "mma.sync.aligned.m16n8k16.row.col.f32.bf16.bf16.f32 "
        "{%0,%1,%2,%3}, {%4,%5,%6,%7}, {%8,%9}, {%0,%1,%2,%3};\n"
        : "+f"(c[0]), "+f"(c[1]), "+f"(c[2]), "+f"(c[3])
        : "r"(a[0]), "r"(a[1]), "r"(a[2]), "r"(a[3]), "r"(b0), "r"(b1));
}

__device__ __forceinline__ void ldsm_x4(uint32_t* r, uint32_t addr) {
    asm volatile(
        "ldmatrix.sync.aligned.m8n8.x4.shared.b16 {%0,%1,%2,%3}, [%4];"
        : "=r"(r[0]), "=r"(r[1]), "=r"(r[2]), "=r"(r[3]) : "r"(addr));
}

__device__ __forceinline__ void ldsm_x4_t(uint32_t* r, uint32_t addr) {
    asm volatile(
        "ldmatrix.sync.aligned.m8n8.x4.trans.shared.b16 {%0,%1,%2,%3}, [%4];"
        : "=r"(r[0]), "=r"(r[1]), "=r"(r[2]), "=r"(r[3]) : "r"(addr));
}

__device__ __forceinline__ uint32_t smem_u32(const void* p) {
    uint32_t a;
    asm("{ .reg .u64 t; cvta.to.shared.u64 t, %1; cvt.u32.u64 %0, t; }"
        : "=r"(a) : "l"(p));
    return a;
}

__device__ __forceinline__ void cp_async16(uint32_t dst, const void* src) {
    asm volatile("cp.async.cg.shared.global [%0], [%1], 16;"
                 :: "r"(dst), "l"(src));
}
__device__ __forceinline__ void cp_commit() {
    asm volatile("cp.async.commit_group;");
}
template <int N> __device__ __forceinline__ void cp_wait() {
    asm volatile("cp.async.wait_group %0;" :: "n"(N));
}

__device__ __forceinline__ void split2(float x, float y,
                                       uint32_t& hi, uint32_t& lo) {
    __nv_bfloat16 hx = __float2bfloat16(x);
    __nv_bfloat16 hy = __float2bfloat16(y);
    __nv_bfloat162 h = __halves2bfloat162(hx, hy);
    __nv_bfloat162 l = __halves2bfloat162(
        __float2bfloat16(x - __bfloat162float(hx)),
        __float2bfloat16(y - __bfloat162float(hy)));
    hi = *(uint32_t*)&h;
    lo = *(uint32_t*)&l;
}

// ===========================================================================
// Fused split: all 5 fp32 tensors -> bf16 hi/lo planes in ONE launch.
// ===========================================================================
#define NX4 (MROWS * DMODEL / 4)      // 1048576
#define NW4 (DMODEL * DMODEL / 4)     // 262144 = 2^18
#define NSPLIT4 (NX4 + 4 * NW4)       // 2097152

__global__ __launch_bounds__(256) void split_all(
    const float* __restrict__ x,  const float* __restrict__ wq,
    const float* __restrict__ wk, const float* __restrict__ wv,
    const float* __restrict__ wo)
{
    int i = blockIdx.x * 256 + threadIdx.x;
    if (i >= NSPLIT4) return;
    const float* src;
    __nv_bfloat16 *hi, *lo;
    int j;
    if (i < NX4) {
        src = x; hi = g_xh; lo = g_xl; j = i;
    } else {
        int r = i - NX4;
        int w = r >> 18;
        j = r & (NW4 - 1);
        switch (w) {
            case 0:  src = wq; hi = g_Wqh; lo = g_Wql; break;
            case 1:  src = wk; hi = g_Wkh; lo = g_Wkl; break;
            case 2:  src = wv; hi = g_Wvh; lo = g_Wvl; break;
            default: src = wo; hi = g_Woh; lo = g_Wol; break;
        }
    }
    float4 v = ((const float4*)src)[j];
    uint32_t h0, l0, h1, l1;
    split2(v.x, v.y, h0, l0);
    split2(v.z, v.w, h1, l1);
    ((uint32_t*)hi)[2 * j + 0] = h0;
    ((uint32_t*)hi)[2 * j + 1] = h1;
    ((uint32_t*)lo)[2 * j + 0] = l0;
    ((uint32_t*)lo)[2 * j + 1] = l1;
}

// ===========================================================================
// bf16x2 GEMM (R8 structure; MMA block permuted to same-acc spacing 4):
// out = A[M,K] @ W[N,K]^T + bias. CTA 128x128, BK=32, 256 thr, 2 CTA/SM.
// final=0: z=0/1/2 -> Wq/Wk/Wv, A=x planes, write Q/K/V planes [B,H,S,HD]
// final=1: A=g_O planes, W=Wo, write fp32 out [M,N]
// ===========================================================================
#define GPLB 10240                 // plane bytes: 128 rows * 40 bf16 * 2
#define GSTAGE (4 * GPLB)          // 40960
#define G_SMEM (2 * GSTAGE)        // 81920

__global__ __launch_bounds__(256, 2) void gemm_bf16x2(
    const float* __restrict__ bq, const float* __restrict__ bk,
    const float* __restrict__ bv, const float* __restrict__ bo,
    float* __restrict__ out, int final_)
{
    extern __shared__ char sm[];
    const uint32_t sbase = smem_u32(sm);

    const int mode = final_ ? 0 : (int)blockIdx.z + 1;
    const __nv_bfloat16 *Agh, *Agl, *Bgh, *Bgl;
    const float* bias;
    if (mode == 0)      { Agh = g_Oh; Agl = g_Ol; Bgh = g_Woh; Bgl = g_Wol; bias = bo; }
    else if (mode == 1) { Agh = g_xh; Agl = g_xl; Bgh = g_Wqh; Bgl = g_Wql; bias = bq; }
    else if (mode == 2) { Agh = g_xh; Agl = g_xl; Bgh = g_Wkh; Bgl = g_Wkl; bias = bk; }
    else                { Agh = g_xh; Agl = g_xl; Bgh = g_Wvh; Bgl = g_Wvl; bias = bv; }

    const int tid  = threadIdx.x;
    const int lane = tid & 31;
    const int wid  = tid >> 5;
    const int wm   = wid & 3;
    const int wn   = wid >> 2;
    const int g    = lane >> 2;
    const int t    = lane & 3;
    const int lr   = lane & 15;
    const int lk   = (lane >> 4) << 3;
    const int row0 = blockIdx.y * 128;
    const int col0 = blockIdx.x * 128;

    float acc[2][8][4];
#pragma unroll
    for (int i = 0; i < 2; i++)
#pragma unroll
        for (int j = 0; j < 8; j++)
#pragma unroll
            for (int q = 0; q < 4; q++) acc[i][j][q] = 0.0f;

    auto ld_stage = [&](int s, int kt) {
        const int kb = kt * 32;
        const uint32_t sb2 = sbase + s * GSTAGE;
#pragma unroll
        for (int i = 0; i < 2; i++) {
            int f = tid + i * 256;
            int r = f >> 2;
            int c = (f & 3) * 8;
            uint32_t o2 = (uint32_t)(r * 80 + c * 2);
            size_t ga = (size_t)(row0 + r) * DMODEL + kb + c;
            size_t gb = (size_t)(col0 + r) * DMODEL + kb + c;
            cp_async16(sb2 + o2,             Agh + ga);
            cp_async16(sb2 + GPLB + o2,      Agl + ga);
            cp_async16(sb2 + 2 * GPLB + o2,  Bgh + gb);
            cp_async16(sb2 + 3 * GPLB + o2,  Bgl + gb);
        }
    };

    ld_stage(0, 0);
    cp_commit();

    const int NS = DMODEL / 32;   // 32
    for (int kt = 0; kt < NS; kt++) {
        if (kt + 1 < NS) {
            ld_stage((kt + 1) & 1, kt + 1);
            cp_commit();
            cp_wait<1>();
        } else {
            cp_wait<0>();
        }
        __syncthreads();

        const uint32_t stb = sbase + (kt & 1) * GSTAGE;

#pragma unroll
        for (int kk = 0; kk < 2; kk++) {
            uint32_t ah[2][4], al[2][4];
#pragma unroll
            for (int mt = 0; mt < 2; mt++) {
                uint32_t ao = stb +
                    (uint32_t)(((wm * 32 + mt * 16 + lr) * 40 + kk * 16 + lk) * 2);
                ldsm_x4(ah[mt], ao);
                ldsm_x4(al[mt], ao + GPLB);
            }
#pragma unroll
            for (int np = 0; np < 4; np++) {
                uint32_t bh[4], bl[4];
                uint32_t bo_ = stb + 2 * GPLB +
                    (uint32_t)(((wn * 64 + np * 16 + lr) * 40 + kk * 16 + lk) * 2);
                ldsm_x4(bh, bo_);
                ldsm_x4(bl, bo_ + GPLB);
                // Permuted: term-major over (hh, hl, lh); same-acc spacing 4.
                // Same operands live as R8 — register demand unchanged.
#pragma unroll
                for (int mt = 0; mt < 2; mt++) {
                    mma_bf16(acc[mt][2 * np],     ah[mt], bh[0], bh[2]);
                    mma_bf16(acc[mt][2 * np + 1], ah[mt], bh[1], bh[3]);
                }
#pragma unroll
                for (int mt = 0; mt < 2; mt++) {
                    mma_bf16(acc[mt][2 * np],     ah[mt], bl[0], bl[2]);
                    mma_bf16(acc[mt][2 * np + 1], ah[mt], bl[1], bl[3]);
                }
#pragma unroll
                for (int mt = 0; mt < 2; mt++) {
                    mma_bf16(acc[mt][2 * np],     al[mt], bh[0], bh[2]);
                    mma_bf16(acc[mt][2 * np + 1], al[mt], bh[1], bh[3]);
                }
            }
        }
        __syncthreads();
    }

    // Epilogue
    __nv_bfloat16* Dh = (mode == 1) ? g_Qh : (mode == 2) ? g_Kh : g_Vh;
    __nv_bfloat16* Dl = (mode == 1) ? g_Ql : (mode == 2) ? g_Kl : g_Vl;
#pragma unroll
    for (int mt = 0; mt < 2; mt++) {
#pragma unroll
        for (int h = 0; h < 2; h++) {
            const int m = row0 + wm * 32 + mt * 16 + g + h * 8;
            const int b_ = m >> 11;
            const int s_ = m & 2047;
#pragma unroll
            for (int nt = 0; nt < 8; nt++) {
                const int n = col0 + wn * 64 + nt * 8 + 2 * t;
                float vx = acc[mt][nt][h * 2 + 0] + bias[n + 0];
                float vy = acc[mt][nt][h * 2 + 1] + bias[n + 1];
                if (mode == 0) {
                    float2 v; v.x = vx; v.y = vy;
                    *(float2*)(out + (size_t)m * DMODEL + n) = v;
                } else {
                    const int hh = n >> 6, d = n & 63;
                    size_t idx = (((size_t)(b_ * HEADS + hh)) * SEQ + s_) * HD + d;
                    uint32_t hi, lo;
                    split2(vx, vy, hi, lo);
                    *(uint32_t*)(Dh + idx) = hi;
                    *(uint32_t*)(Dl + idx) = lo;
                }
            }
        }
    }
}

// ===========================================================================
// Flash attention (R8 structure; MMA blocks permuted to same-acc spacing 2),
// bf16x2 mma, P & Q in regs. Grid (SEQ/128, B*H), 256 thr, 2 CTAs/SM.
// ===========================================================================
#define AST(st) ((st) * 36864)
#define ATT_SMEM 73728

__global__ __launch_bounds__(256, 2) void attn_bf16x2()
{
    extern __shared__ char sm[];
    const uint32_t sb = smem_u32(sm);

    const int tid  = threadIdx.x;
    const int lane = tid & 31;
    const int wid  = tid >> 5;
    const int g    = lane >> 2;
    const int t    = lane & 3;
    const int lr   = lane & 15;
    const int lh   = lane >> 4;        // 0/1
    const int qt   = blockIdx.x;       // 0..15
    const int bh   = blockIdx.y;       // 0..31

    // ---- Q fragments in registers (loaded once) ----
    uint32_t qh[4][4], ql[4][4];
    {
        const size_t base = ((size_t)bh * SEQ + qt * 128 + wid * 16) * HD;
        const __nv_bfloat16* Qh = g_Qh + base;
        const __nv_bfloat16* Ql = g_Ql + base;
#pragma unroll
        for (int kk = 0; kk < 4; kk++) {
            const int d0 = kk * 16 + 2 * t;
            qh[kk][0] = *(const uint32_t*)(Qh + g * HD + d0);
            qh[kk][1] = *(const uint32_t*)(Qh + (g + 8) * HD + d0);
            qh[kk][2] = *(const uint32_t*)(Qh + g * HD + d0 + 8);
            qh[kk][3] = *(const uint32_t*)(Qh + (g + 8) * HD + d0 + 8);
            ql[kk][0] = *(const uint32_t*)(Ql + g * HD + d0);
            ql[kk][1] = *(const uint32_t*)(Ql + (g + 8) * HD + d0);
            ql[kk][2] = *(const uint32_t*)(Ql + g * HD + d0 + 8);
            ql[kk][3] = *(const uint32_t*)(Ql + (g + 8) * HD + d0 + 8);
        }
    }

    auto ld_kv = [&](int st, int ck) {
        const size_t go = ((size_t)bh * SEQ + (size_t)ck * 64) * HD;
        const uint32_t base = sb + AST(st);
#pragma unroll
        for (int i = 0; i < 2; i++) {
            int f = tid + i * 256;
            int r = f >> 3, c = f & 7;
            uint32_t o2 = (uint32_t)(r * 144 + c * 16);
            size_t gi = go + r * 64 + c * 8;
            cp_async16(base + o2,          g_Kh + gi);
            cp_async16(base + 9216 + o2,   g_Kl + gi);
            cp_async16(base + 18432 + o2,  g_Vh + gi);
            cp_async16(base + 27648 + o2,  g_Vl + gi);
        }
    };

    ld_kv(0, 0); cp_commit();
    ld_kv(1, 1); cp_commit();

    float o[8][4];
#pragma unroll
    for (int nt = 0; nt < 8; nt++)
#pragma unroll
        for (int q = 0; q < 4; q++) o[nt][q] = 0.0f;
    float mrow[2] = {-1e30f, -1e30f};
    float lrow[2] = {0.0f, 0.0f};
    const float scale = 0.125f;

    for (int ck = 0; ck < SEQ / 64; ck++) {
        if (ck >= SEQ / 64 - 2) cp_wait<0>(); else cp_wait<1>();
        __syncthreads();

        const uint32_t kpl = sb + AST(ck & 1);
        const uint32_t vpl = kpl + 18432;

        // ---- QK^T ----
        float s[8][4];
#pragma unroll
        for (int nt = 0; nt < 8; nt++)
#pragma unroll
            for (int q = 0; q < 4; q++) s[nt][q] = 0.0f;

#pragma unroll
        for (int kk = 0; kk < 4; kk++) {
#pragma unroll
            for (int np = 0; np < 4; np++) {
                uint32_t kbh[4], kbl[4];
                uint32_t ko = kpl +
                    (uint32_t)(((np * 16 + lr) * 72 + kk * 16 + lh * 8) * 2);
                ldsm_x4(kbh, ko);
                ldsm_x4(kbl, ko + 9216);
                // Permuted: term-major; same-acc spacing 2.
                mma_bf16(s[2 * np],     qh[kk], kbh[0], kbh[2]);
                mma_bf16(s[2 * np + 1], qh[kk], kbh[1], kbh[3]);
                mma_bf16(s[2 * np],     qh[kk], kbl[0], kbl[2]);
                mma_bf16(s[2 * np + 1], qh[kk], kbl[1], kbl[3]);
                mma_bf16(s[2 * np],     ql[kk], kbh[0], kbh[2]);
                mma_bf16(s[2 * np + 1], ql[kk], kbh[1], kbh[3]);
            }
        }

        // ---- online softmax (rows g, g+8; warp-local over t lanes) ----
#pragma unroll
        for (int nt = 0; nt < 8; nt++)
#pragma unroll
            for (int q = 0; q < 4; q++) s[nt][q] *= scale;

#pragma unroll
        for (int h = 0; h < 2; h++) {
            float mx = -1e30f;
#pragma unroll
            for (int nt = 0; nt < 8; nt++) {
                mx = fmaxf(mx, s[nt][h * 2 + 0]);
                mx = fmaxf(mx, s[nt][h * 2 + 1]);
            }
            mx = fmaxf(mx, __shfl_xor_sync(0xffffffffu, mx, 1));
            mx = fmaxf(mx, __shfl_xor_sync(0xffffffffu, mx, 2));
            const float mnew  = fmaxf(mrow[h], mx);
            const float alpha = __expf(mrow[h] - mnew);
            float rsum = 0.0f;
#pragma unroll
            for (int nt = 0; nt < 8; nt++) {
                float p0 = __expf(s[nt][h * 2 + 0] - mnew);
                float p1 = __expf(s[nt][h * 2 + 1] - mnew);
                s[nt][h * 2 + 0] = p0;
                s[nt][h * 2 + 1] = p1;
                rsum += p0 + p1;
            }
            rsum += __shfl_xor_sync(0xffffffffu, rsum, 1);
            rsum += __shfl_xor_sync(0xffffffffu, rsum, 2);
            lrow[h] = lrow[h] * alpha + rsum;
            mrow[h] = mnew;
#pragma unroll
            for (int nt = 0; nt < 8; nt++) {
                o[nt][h * 2 + 0] *= alpha;
                o[nt][h * 2 + 1] *= alpha;
            }
        }

        // ---- O += P @ V  (P repacked C->A frags in registers) ----
#pragma unroll
        for (int kk = 0; kk < 4; kk++) {
            uint32_t ph[4], pl[4];
            split2(s[2 * kk][0],     s[2 * kk][1],     ph[0], pl[0]);
            split2(s[2 * kk][2],     s[2 * kk][3],     ph[1], pl[1]);
            split2(s[2 * kk + 1][0], s[2 * kk + 1][1], ph[2], pl[2]);
            split2(s[2 * kk + 1][2], s[2 * kk + 1][3], ph[3], pl[3]);
#pragma unroll
            for (int np = 0; np < 4; np++) {
                uint32_t vbh[4], vbl[4];
                uint32_t vo = vpl +
                    (uint32_t)((kk * 16 + lr) * 144 + np * 32 + lh * 16);
                ldsm_x4_t(vbh, vo);
                ldsm_x4_t(vbl, vo + 9216);
                // Permuted: term-major; same-acc spacing 2.
                mma_bf16(o[2 * np],     ph, vbh[0], vbh[1]);
                mma_bf16(o[2 * np + 1], ph, vbh[2], vbh[3]);
                mma_bf16(o[2 * np],     ph, vbl[0], vbl[1]);
                mma_bf16(o[2 * np + 1], ph, vbl[2], vbl[3]);
                mma_bf16(o[2 * np],     pl, vbh[0], vbh[1]);
                mma_bf16(o[2 * np + 1], pl, vbh[2], vbh[3]);
            }
        }
        __syncthreads();
        if (ck + 2 < SEQ / 64) { ld_kv(ck & 1, ck + 2); cp_commit(); }
    }

    // ---- epilogue: split & write to g_O planes [B,S,D] ----
    const int b_ = bh >> 4;
    const int h_ = bh & 15;
#pragma unroll
    for (int h = 0; h < 2; h++) {
        const float inv = 1.0f / lrow[h];
        const int srow = qt * 128 + wid * 16 + g + h * 8;
        const size_t ro = ((size_t)(b_ * SEQ + srow)) * DMODEL + h_ * 64;
#pragma unroll
        for (int nt = 0; nt < 8; nt++) {
            float vx = o[nt][h * 2 + 0] * inv;
            float vy = o[nt][h * 2 + 1] * inv;
            uint32_t hi, lo;
            split2(vx, vy, hi, lo);
            *(uint32_t*)(g_Oh + ro + nt * 8 + 2 * t) = hi;
            *(uint32_t*)(g_Ol + ro + nt * 8 + 2 * t) = lo;
        }
    }
}

// ---------------------------------------------------------------------------
extern "C" void kernel_launch(void* const* d_in, const int* in_sizes, int n_in,
                              void* d_out, int out_size)
{
    const float* x  = (const float*)d_in[0];
    const float* Wq = (const float*)d_in[1];
    const float* bq = (const float*)d_in[2];
    const float* Wk = (const float*)d_in[3];
    const float* bk = (const float*)d_in[4];
    const float* Wv = (const float*)d_in[5];
    const float* bv = (const float*)d_in[6];
    const float* Wo = (const float*)d_in[7];
    const float* bo = (const float*)d_in[8];
    float* out = (float*)d_out;

    static int attr_set = 0;
    if (!attr_set) {
        cudaFuncSetAttribute(gemm_bf16x2,
                             cudaFuncAttributeMaxDynamicSharedMemorySize,
                             G_SMEM);
        cudaFuncSetAttribute(attn_bf16x2,
                             cudaFuncAttributeMaxDynamicSharedMemorySize,
                             ATT_SMEM);
        attr_set = 1;
    }

    // Fused splits: fp32 -> bf16 hi/lo planes (one launch)
    split_all<<<(NSPLIT4 + 255) / 256, 256>>>(x, Wq, Wk, Wv, Wo);

    // Fused QKV projections (z selects Wq/Wk/Wv)
    gemm_bf16x2<<<dim3(DMODEL / 128, MROWS / 128, 3), 256, G_SMEM>>>(
        bq, bk, bv, nullptr, nullptr, 0);

    attn_bf16x2<<<dim3(SEQ / 128, BATCH * HEADS), 256, ATT_SMEM>>>();

    // Output projection
    gemm_bf16x2<<<dim3(DMODEL / 128, MROWS / 128, 1), 256, G_SMEM>>>(
        nullptr, nullptr, nullptr, bo, out, 1);
}

// round 12
// speedup vs baseline: 1.5609x; 1.0169x over previous
#include <cuda_runtime.h>
#include <cuda_bf16.h>
#include <cstdint>

// Problem constants
#define BATCH   2
#define HEADS   16
#define SEQ     2048
#define HD      64
#define DMODEL  1024
#define MROWS   (BATCH * SEQ)   // 4096

// ===========================================================================
// Global scratch (allocation-free rule: __device__ globals). bf16 hi/lo planes.
// ===========================================================================
__device__ __nv_bfloat16 g_xh[MROWS * DMODEL], g_xl[MROWS * DMODEL];
__device__ __nv_bfloat16 g_Wqh[DMODEL * DMODEL], g_Wql[DMODEL * DMODEL];
__device__ __nv_bfloat16 g_Wkh[DMODEL * DMODEL], g_Wkl[DMODEL * DMODEL];
__device__ __nv_bfloat16 g_Wvh[DMODEL * DMODEL], g_Wvl[DMODEL * DMODEL];
__device__ __nv_bfloat16 g_Woh[DMODEL * DMODEL], g_Wol[DMODEL * DMODEL];
__device__ __nv_bfloat16 g_Qh[MROWS * DMODEL], g_Ql[MROWS * DMODEL];  // [B,H,S,HD]
__device__ __nv_bfloat16 g_Kh[MROWS * DMODEL], g_Kl[MROWS * DMODEL];
__device__ __nv_bfloat16 g_Vh[MROWS * DMODEL], g_Vl[MROWS * DMODEL];
__device__ __nv_bfloat16 g_Oh[MROWS * DMODEL], g_Ol[MROWS * DMODEL];  // [B,S,D]

// ===========================================================================
// PTX helpers
// ===========================================================================
// volatile on purpose: keeps ptxas from hoisting/reordering fragment loads
// in ways that extend live ranges past the reg cap (R7/R9 lesson).
__device__ __forceinline__ void mma_bf16(float* c, const uint32_t* a,
                                         uint32_t b0, uint32_t b1) {
    asm volatile(
        "mma.sync.aligned.m16n8k16.row.col.f32.bf16.bf16.f32 "
        "{%0,%1,%2,%3}, {%4,%5,%6,%7}, {%8,%9}, {%0,%1,%2,%3};\n"
        : "+f"(c[0]), "+f"(c[1]), "+f"(c[2]), "+f"(c[3])
        : "r"(a[0]), "r"(a[1]), "r"(a[2]), "r"(a[3]), "r"(b0), "r"(b1));
}

__device__ __forceinline__ void ldsm_x4(uint32_t* r, uint32_t addr) {
    asm volatile(
        "ldmatrix.sync.aligned.m8n8.x4.shared.b16 {%0,%1,%2,%3}, [%4];"
        : "=r"(r[0]), "=r"(r[1]), "=r"(r[2]), "=r"(r[3]) : "r"(addr));
}

__device__ __forceinline__ void ldsm_x4_t(uint32_t* r, uint32_t addr) {
    asm volatile(
        "ldmatrix.sync.aligned.m8n8.x4.trans.shared.b16 {%0,%1,%2,%3}, [%4];"
        : "=r"(r[0]), "=r"(r[1]), "=r"(r[2]), "=r"(r[3]) : "r"(addr));
}

__device__ __forceinline__ uint32_t smem_u32(const void* p) {
    uint32_t a;
    asm("{ .reg .u64 t; cvta.to.shared.u64 t, %1; cvt.u32.u64 %0, t; }"
        : "=r"(a) : "l"(p));
    return a;
}

__device__ __forceinline__ void cp_async16(uint32_t dst, const void* src) {
    asm volatile("cp.async.cg.shared.global [%0], [%1], 16;"
                 :: "r"(dst), "l"(src));
}
__device__ __forceinline__ void cp_commit() {
    asm volatile("cp.async.commit_group;");
}
template <int N> __device__ __forceinline__ void cp_wait() {
    asm volatile("cp.async.wait_group %0;" :: "n"(N));
}

__device__ __forceinline__ void split2(float x, float y,
                                       uint32_t& hi, uint32_t& lo) {
    __nv_bfloat16 hx = __float2bfloat16(x);
    __nv_bfloat16 hy = __float2bfloat16(y);
    __nv_bfloat162 h = __halves2bfloat162(hx, hy);
    __nv_bfloat162 l = __halves2bfloat162(
        __float2bfloat16(x - __bfloat162float(hx)),
        __float2bfloat16(y - __bfloat162float(hy)));
    hi = *(uint32_t*)&h;
    lo = *(uint32_t*)&l;
}

// ===========================================================================
// Fused split: all 5 fp32 tensors -> bf16 hi/lo planes in ONE launch.
// ===========================================================================
#define NX4 (MROWS * DMODEL / 4)      // 1048576
#define NW4 (DMODEL * DMODEL / 4)     // 262144 = 2^18
#define NSPLIT4 (NX4 + 4 * NW4)       // 2097152

__global__ __launch_bounds__(256) void split_all(
    const float* __restrict__ x,  const float* __restrict__ wq,
    const float* __restrict__ wk, const float* __restrict__ wv,
    const float* __restrict__ wo)
{
    int i = blockIdx.x * 256 + threadIdx.x;
    if (i >= NSPLIT4) return;
    const float* src;
    __nv_bfloat16 *hi, *lo;
    int j;
    if (i < NX4) {
        src = x; hi = g_xh; lo = g_xl; j = i;
    } else {
        int r = i - NX4;
        int w = r >> 18;
        j = r & (NW4 - 1);
        switch (w) {
            case 0:  src = wq; hi = g_Wqh; lo = g_Wql; break;
            case 1:  src = wk; hi = g_Wkh; lo = g_Wkl; break;
            case 2:  src = wv; hi = g_Wvh; lo = g_Wvl; break;
            default: src = wo; hi = g_Woh; lo = g_Wol; break;
        }
    }
    float4 v = ((const float4*)src)[j];
    uint32_t h0, l0, h1, l1;
    split2(v.x, v.y, h0, l0);
    split2(v.z, v.w, h1, l1);
    ((uint32_t*)hi)[2 * j + 0] = h0;
    ((uint32_t*)hi)[2 * j + 1] = h1;
    ((uint32_t*)lo)[2 * j + 0] = l0;
    ((uint32_t*)lo)[2 * j + 1] = l1;
}

// ===========================================================================
// bf16x2 GEMM v2: CTA tile 128x256, BK=32, 512 threads (16 warps, 4m x 4n),
// warp tile 32x64 (identical per-warp code/regs to the proven R8 form).
// 3-stage cp.async pipeline, ONE __syncthreads per k-stage. 1 CTA/SM.
// final=0: z=0/1/2 -> Wq/Wk/Wv, A=x planes, write Q/K/V planes [B,H,S,HD]
// final=1: A=g_O planes, W=Wo, write fp32 out [M,N]
// Stage layout: Ah[128][40] | Al | Bh[256][40] | Bl  (10240,10240,20480,20480)
// ===========================================================================
#define GSTG   61440               // bytes per stage
#define G_SMEM (3 * GSTG)          // 184320

__global__ __launch_bounds__(512, 1) void gemm_bf16x2(
    const float* __restrict__ bq, const float* __restrict__ bk,
    const float* __restrict__ bv, const float* __restrict__ bo,
    float* __restrict__ out, int final_)
{
    extern __shared__ char sm[];
    const uint32_t sbase = smem_u32(sm);

    const int mode = final_ ? 0 : (int)blockIdx.z + 1;
    const __nv_bfloat16 *Agh, *Agl, *Bgh, *Bgl;
    const float* bias;
    if (mode == 0)      { Agh = g_Oh; Agl = g_Ol; Bgh = g_Woh; Bgl = g_Wol; bias = bo; }
    else if (mode == 1) { Agh = g_xh; Agl = g_xl; Bgh = g_Wqh; Bgl = g_Wql; bias = bq; }
    else if (mode == 2) { Agh = g_xh; Agl = g_xl; Bgh = g_Wkh; Bgl = g_Wkl; bias = bk; }
    else                { Agh = g_xh; Agl = g_xl; Bgh = g_Wvh; Bgl = g_Wvl; bias = bv; }

    const int tid  = threadIdx.x;
    const int lane = tid & 31;
    const int wid  = tid >> 5;
    const int wm   = wid & 3;          // 0..3  (m)
    const int wn   = wid >> 2;         // 0..3  (n)
    const int g    = lane >> 2;
    const int t    = lane & 3;
    const int lr   = lane & 15;
    const int lk   = (lane >> 4) << 3;
    const int row0 = blockIdx.y * 128;
    const int col0 = blockIdx.x * 256;

    float acc[2][8][4];
#pragma unroll
    for (int i = 0; i < 2; i++)
#pragma unroll
        for (int j = 0; j < 8; j++)
#pragma unroll
            for (int q = 0; q < 4; q++) acc[i][j][q] = 0.0f;

    auto ld_stage = [&](int s, int kt) {
        const int kb = kt * 32;
        const uint32_t sb2 = sbase + s * GSTG;
        {   // A planes: 128 rows x 4 chunks = 512 -> 1 chunk/thread/plane
            int r = tid >> 2;
            int c = (tid & 3) * 8;
            uint32_t o2 = (uint32_t)(r * 80 + c * 2);
            size_t ga = (size_t)(row0 + r) * DMODEL + kb + c;
            cp_async16(sb2 + o2,          Agh + ga);
            cp_async16(sb2 + 10240 + o2,  Agl + ga);
        }
#pragma unroll
        for (int i = 0; i < 2; i++) {   // B planes: 256 rows x 4 chunks = 1024
            int f = tid + i * 512;
            int r = f >> 2;
            int c = (f & 3) * 8;
            uint32_t o2 = (uint32_t)(r * 80 + c * 2);
            size_t gb = (size_t)(col0 + r) * DMODEL + kb + c;
            cp_async16(sb2 + 20480 + o2,  Bgh + gb);
            cp_async16(sb2 + 40960 + o2,  Bgl + gb);
        }
    };

    // Prologue: stages 0 and 1 in flight (prefetch distance 2)
    ld_stage(0, 0); cp_commit();
    ld_stage(1, 1); cp_commit();

    const int NS = DMODEL / 32;   // 32
    int sidx = 0;                 // stage buffer index of kt
    for (int kt = 0; kt < NS; kt++) {
        // stage kt ready?  pending groups at entry: {kt, kt+1}
        if (kt + 1 < NS) cp_wait<1>(); else cp_wait<0>();
        __syncthreads();   // data visible to all; all warps done with kt-1

        // issue loads for kt+2 into the buffer freed by stage kt-1
        if (kt + 2 < NS) {
            int s2 = sidx + 2; if (s2 >= 3) s2 -= 3;
            ld_stage(s2, kt + 2);
            cp_commit();
        }

        const uint32_t stb = sbase + sidx * GSTG;

#pragma unroll
        for (int kk = 0; kk < 2; kk++) {
            uint32_t ah[2][4], al[2][4];
#pragma unroll
            for (int mt = 0; mt < 2; mt++) {
                uint32_t ao = stb +
                    (uint32_t)(((wm * 32 + mt * 16 + lr) * 40 + kk * 16 + lk) * 2);
                ldsm_x4(ah[mt], ao);
                ldsm_x4(al[mt], ao + 10240);
            }
#pragma unroll
            for (int np = 0; np < 4; np++) {
                uint32_t bh[4], bl[4];
                uint32_t bo_ = stb + 20480 +
                    (uint32_t)(((wn * 64 + np * 16 + lr) * 40 + kk * 16 + lk) * 2);
                ldsm_x4(bh, bo_);
                ldsm_x4(bl, bo_ + 20480);
#pragma unroll
                for (int mt = 0; mt < 2; mt++) {
                    mma_bf16(acc[mt][2 * np],     ah[mt], bh[0], bh[2]);
                    mma_bf16(acc[mt][2 * np],     ah[mt], bl[0], bl[2]);
                    mma_bf16(acc[mt][2 * np],     al[mt], bh[0], bh[2]);
                    mma_bf16(acc[mt][2 * np + 1], ah[mt], bh[1], bh[3]);
                    mma_bf16(acc[mt][2 * np + 1], ah[mt], bl[1], bl[3]);
                    mma_bf16(acc[mt][2 * np + 1], al[mt], bh[1], bh[3]);
                }
            }
        }
        if (++sidx == 3) sidx = 0;
    }

    // Epilogue
    __nv_bfloat16* Dh = (mode == 1) ? g_Qh : (mode == 2) ? g_Kh : g_Vh;
    __nv_bfloat16* Dl = (mode == 1) ? g_Ql : (mode == 2) ? g_Kl : g_Vl;
#pragma unroll
    for (int mt = 0; mt < 2; mt++) {
#pragma unroll
        for (int h = 0; h < 2; h++) {
            const int m = row0 + wm * 32 + mt * 16 + g + h * 8;
            const int b_ = m >> 11;
            const int s_ = m & 2047;
#pragma unroll
            for (int nt = 0; nt < 8; nt++) {
                const int n = col0 + wn * 64 + nt * 8 + 2 * t;
                float vx = acc[mt][nt][h * 2 + 0] + bias[n + 0];
                float vy = acc[mt][nt][h * 2 + 1] + bias[n + 1];
                if (mode == 0) {
                    float2 v; v.x = vx; v.y = vy;
                    *(float2*)(out + (size_t)m * DMODEL + n) = v;
                } else {
                    const int hh = n >> 6, d = n & 63;
                    size_t idx = (((size_t)(b_ * HEADS + hh)) * SEQ + s_) * HD + d;
                    uint32_t hi, lo;
                    split2(vx, vy, hi, lo);
                    *(uint32_t*)(Dh + idx) = hi;
                    *(uint32_t*)(Dl + idx) = lo;
                }
            }
        }
    }
}

// ===========================================================================
// Flash attention (R8/R10-proven form, untouched), bf16x2 mma, P & Q in regs.
// Grid (SEQ/128, B*H), 256 threads (8 warps), 2 CTAs/SM.
// ===========================================================================
#define AST(st) ((st) * 36864)
#define ATT_SMEM 73728

__global__ __launch_bounds__(256, 2) void attn_bf16x2()
{
    extern __shared__ char sm[];
    const uint32_t sb = smem_u32(sm);

    const int tid  = threadIdx.x;
    const int lane = tid & 31;
    const int wid  = tid >> 5;
    const int g    = lane >> 2;
    const int t    = lane & 3;
    const int lr   = lane & 15;
    const int lh   = lane >> 4;        // 0/1
    const int qt   = blockIdx.x;       // 0..15
    const int bh   = blockIdx.y;       // 0..31

    // ---- Q fragments in registers (loaded once) ----
    uint32_t qh[4][4], ql[4][4];
    {
        const size_t base = ((size_t)bh * SEQ + qt * 128 + wid * 16) * HD;
        const __nv_bfloat16* Qh = g_Qh + base;
        const __nv_bfloat16* Ql = g_Ql + base;
#pragma unroll
        for (int kk = 0; kk < 4; kk++) {
            const int d0 = kk * 16 + 2 * t;
            qh[kk][0] = *(const uint32_t*)(Qh + g * HD + d0);
            qh[kk][1] = *(const uint32_t*)(Qh + (g + 8) * HD + d0);
            qh[kk][2] = *(const uint32_t*)(Qh + g * HD + d0 + 8);
            qh[kk][3] = *(const uint32_t*)(Qh + (g + 8) * HD + d0 + 8);
            ql[kk][0] = *(const uint32_t*)(Ql + g * HD + d0);
            ql[kk][1] = *(const uint32_t*)(Ql + (g + 8) * HD + d0);
            ql[kk][2] = *(const uint32_t*)(Ql + g * HD + d0 + 8);
            ql[kk][3] = *(const uint32_t*)(Ql + (g + 8) * HD + d0 + 8);
        }
    }

    auto ld_kv = [&](int st, int ck) {
        const size_t go = ((size_t)bh * SEQ + (size_t)ck * 64) * HD;
        const uint32_t base = sb + AST(st);
#pragma unroll
        for (int i = 0; i < 2; i++) {
            int f = tid + i * 256;
            int r = f >> 3, c = f & 7;
            uint32_t o2 = (uint32_t)(r * 144 + c * 16);
            size_t gi = go + r * 64 + c * 8;
            cp_async16(base + o2,          g_Kh + gi);
            cp_async16(base + 9216 + o2,   g_Kl + gi);
            cp_async16(base + 18432 + o2,  g_Vh + gi);
            cp_async16(base + 27648 + o2,  g_Vl + gi);
        }
    };

    ld_kv(0, 0); cp_commit();
    ld_kv(1, 1); cp_commit();

    float o[8][4];
#pragma unroll
    for (int nt = 0; nt < 8; nt++)
#pragma unroll
        for (int q = 0; q < 4; q++) o[nt][q] = 0.0f;
    float mrow[2] = {-1e30f, -1e30f};
    float lrow[2] = {0.0f, 0.0f};
    const float scale = 0.125f;

    for (int ck = 0; ck < SEQ / 64; ck++) {
        if (ck >= SEQ / 64 - 2) cp_wait<0>(); else cp_wait<1>();
        __syncthreads();

        const uint32_t kpl = sb + AST(ck & 1);
        const uint32_t vpl = kpl + 18432;

        // ---- QK^T ----
        float s[8][4];
#pragma unroll
        for (int nt = 0; nt < 8; nt++)
#pragma unroll
            for (int q = 0; q < 4; q++) s[nt][q] = 0.0f;

#pragma unroll
        for (int kk = 0; kk < 4; kk++) {
#pragma unroll
            for (int np = 0; np < 4; np++) {
                uint32_t kbh[4], kbl[4];
                uint32_t ko = kpl +
                    (uint32_t)(((np * 16 + lr) * 72 + kk * 16 + lh * 8) * 2);
                ldsm_x4(kbh, ko);
                ldsm_x4(kbl, ko + 9216);
                mma_bf16(s[2 * np],     qh[kk], kbh[0], kbh[2]);
                mma_bf16(s[2 * np + 1], qh[kk], kbh[1], kbh[3]);
                mma_bf16(s[2 * np],     qh[kk], kbl[0], kbl[2]);
                mma_bf16(s[2 * np + 1], qh[kk], kbl[1], kbl[3]);
                mma_bf16(s[2 * np],     ql[kk], kbh[0], kbh[2]);
                mma_bf16(s[2 * np + 1], ql[kk], kbh[1], kbh[3]);
            }
        }

        // ---- online softmax (rows g, g+8; warp-local over t lanes) ----
#pragma unroll
        for (int nt = 0; nt < 8; nt++)
#pragma unroll
            for (int q = 0; q < 4; q++) s[nt][q] *= scale;

#pragma unroll
        for (int h = 0; h < 2; h++) {
            float mx = -1e30f;
#pragma unroll
            for (int nt = 0; nt < 8; nt++) {
                mx = fmaxf(mx, s[nt][h * 2 + 0]);
                mx = fmaxf(mx, s[nt][h * 2 + 1]);
            }
            mx = fmaxf(mx, __shfl_xor_sync(0xffffffffu, mx, 1));
            mx = fmaxf(mx, __shfl_xor_sync(0xffffffffu, mx, 2));
            const float mnew  = fmaxf(mrow[h], mx);
            const float alpha = __expf(mrow[h] - mnew);
            float rsum = 0.0f;
#pragma unroll
            for (int nt = 0; nt < 8; nt++) {
                float p0 = __expf(s[nt][h * 2 + 0] - mnew);
                float p1 = __expf(s[nt][h * 2 + 1] - mnew);
                s[nt][h * 2 + 0] = p0;
                s[nt][h * 2 + 1] = p1;
                rsum += p0 + p1;
            }
            rsum += __shfl_xor_sync(0xffffffffu, rsum, 1);
            rsum += __shfl_xor_sync(0xffffffffu, rsum, 2);
            lrow[h] = lrow[h] * alpha + rsum;
            mrow[h] = mnew;
#pragma unroll
            for (int nt = 0; nt < 8; nt++) {
                o[nt][h * 2 + 0] *= alpha;
                o[nt][h * 2 + 1] *= alpha;
            }
        }

        // ---- O += P @ V  (P repacked C->A frags in registers) ----
#pragma unroll
        for (int kk = 0; kk < 4; kk++) {
            uint32_t ph[4], pl[4];
            split2(s[2 * kk][0],     s[2 * kk][1],     ph[0], pl[0]);
            split2(s[2 * kk][2],     s[2 * kk][3],     ph[1], pl[1]);
            split2(s[2 * kk + 1][0], s[2 * kk + 1][1], ph[2], pl[2]);
            split2(s[2 * kk + 1][2], s[2 * kk + 1][3], ph[3], pl[3]);
#pragma unroll
            for (int np = 0; np < 4; np++) {
                uint32_t vbh[4], vbl[4];
                uint32_t vo = vpl +
                    (uint32_t)((kk * 16 + lr) * 144 + np * 32 + lh * 16);
                ldsm_x4_t(vbh, vo);
                ldsm_x4_t(vbl, vo + 9216);
                mma_bf16(o[2 * np],     ph, vbh[0], vbh[1]);
                mma_bf16(o[2 * np + 1], ph, vbh[2], vbh[3]);
                mma_bf16(o[2 * np],     ph, vbl[0], vbl[1]);
                mma_bf16(o[2 * np + 1], ph, vbl[2], vbl[3]);
                mma_bf16(o[2 * np],     pl, vbh[0], vbh[1]);
                mma_bf16(o[2 * np + 1], pl, vbh[2], vbh[3]);
            }
        }
        __syncthreads();
        if (ck + 2 < SEQ / 64) { ld_kv(ck & 1, ck + 2); cp_commit(); }
    }

    // ---- epilogue: split & write to g_O planes [B,S,D] ----
    const int b_ = bh >> 4;
    const int h_ = bh & 15;
#pragma unroll
    for (int h = 0; h < 2; h++) {
        const float inv = 1.0f / lrow[h];
        const int srow = qt * 128 + wid * 16 + g + h * 8;
        const size_t ro = ((size_t)(b_ * SEQ + srow)) * DMODEL + h_ * 64;
#pragma unroll
        for (int nt = 0; nt < 8; nt++) {
            float vx = o[nt][h * 2 + 0] * inv;
            float vy = o[nt][h * 2 + 1] * inv;
            uint32_t hi, lo;
            split2(vx, vy, hi, lo);
            *(uint32_t*)(g_Oh + ro + nt * 8 + 2 * t) = hi;
            *(uint32_t*)(g_Ol + ro + nt * 8 + 2 * t) = lo;
        }
    }
}

// ---------------------------------------------------------------------------
extern "C" void kernel_launch(void* const* d_in, const int* in_sizes, int n_in,
                              void* d_out, int out_size)
{
    const float* x  = (const float*)d_in[0];
    const float* Wq = (const float*)d_in[1];
    const float* bq = (const float*)d_in[2];
    const float* Wk = (const float*)d_in[3];
    const float* bk = (const float*)d_in[4];
    const float* Wv = (const float*)d_in[5];
    const float* bv = (const float*)d_in[6];
    const float* Wo = (const float*)d_in[7];
    const float* bo = (const float*)d_in[8];
    float* out = (float*)d_out;

    static int attr_set = 0;
    if (!attr_set) {
        cudaFuncSetAttribute(gemm_bf16x2,
                             cudaFuncAttributeMaxDynamicSharedMemorySize,
                             G_SMEM);
        cudaFuncSetAttribute(attn_bf16x2,
                             cudaFuncAttributeMaxDynamicSharedMemorySize,
                             ATT_SMEM);
        attr_set = 1;
    }

    // Fused splits: fp32 -> bf16 hi/lo planes (one launch)
    split_all<<<(NSPLIT4 + 255) / 256, 256>>>(x, Wq, Wk, Wv, Wo);

    // Fused QKV projections (z selects Wq/Wk/Wv). CTA tile 128x256.
    gemm_bf16x2<<<dim3(DMODEL / 256, MROWS / 128, 3), 512, G_SMEM>>>(
        bq, bk, bv, nullptr, nullptr, 0);

    attn_bf16x2<<<dim3(SEQ / 128, BATCH * HEADS), 256, ATT_SMEM>>>();

    // Output projection
    gemm_bf16x2<<<dim3(DMODEL / 256, MROWS / 128, 1), 512, G_SMEM>>>(
        nullptr, nullptr, nullptr, bo, out, 1);
}